// round 14
// baseline (speedup 1.0000x reference)
#include <cuda_runtime.h>
#include <math.h>

#define PHq 7
#define PWq 7
#define CC 256
#define HH 50
#define WW 76
#define SCALE 0.0625f
#define WARPS 8
#define CPB 32                 // channels per block
#define CPW (CPB / WARPS)      // 4 channels per warp
#define CHUNKS (CC / CPB)      // 8 chunks per ROI
#define WSTRIDE 24             // padded smem row stride (window <= 22x22 proven)

__global__ __launch_bounds__(256) void roipool_kernel(const float* __restrict__ feats,
                                                      const float* __restrict__ rois,
                                                      float* __restrict__ out) {
    __shared__ float win[WARPS][WSTRIDE * WSTRIDE];   // 18.4 KB
    __shared__ int sh_hs[PHq], sh_he[PHq], sh_ws[PWq], sh_we[PWq];
    __shared__ int sh_r0, sh_c0, sh_nr, sh_boff;

    int n     = blockIdx.x / CHUNKS;
    int chunk = blockIdx.x - n * CHUNKS;
    int t     = threadIdx.x;

    if (t <= PHq + PWq) {
        const float* r = rois + n * 5;
        int b  = (int)r[0];
        // round-half-to-even; *2^-4 exact — matches jnp.round(rois*0.0625)
        int x1 = __float2int_rn(r[1] * SCALE);
        int y1 = __float2int_rn(r[2] * SCALE);
        int x2 = __float2int_rn(r[3] * SCALE);
        int y2 = __float2int_rn(r[4] * SCALE);

        // XLA lowers extent/7.0 as extent * fl32(1/7); replicate exactly.
        const float R7 = 1.0f / 7.0f;
        float bin_h = __fmul_rn((float)max(y2 - y1 + 1, 1), R7);
        float bin_w = __fmul_rn((float)max(x2 - x1 + 1, 1), R7);

        if (t < PHq) {
            int hs = (int)floorf(__fmul_rn((float)t, bin_h)) + y1;
            int he = (int)ceilf (__fmul_rn((float)(t + 1), bin_h)) + y1;
            sh_hs[t] = min(max(hs, 0), HH);
            sh_he[t] = min(max(he, 0), HH);
        }
        if (t >= PHq && t < PHq + PWq) {
            int u = t - PHq;
            int ws = (int)floorf(__fmul_rn((float)u, bin_w)) + x1;
            int we = (int)ceilf (__fmul_rn((float)(u + 1), bin_w)) + x1;
            sh_ws[u] = min(max(ws, 0), WW);
            sh_we[u] = min(max(we, 0), WW);
        }
        if (t == PHq + PWq) {
            sh_boff = b * (CC * HH * WW);
            // window bounds (bin starts/ends are monotone in p)
            int r0 = min(max(y1, 0), HH);
            int r1 = min(max((int)ceilf(__fmul_rn(7.0f, bin_h)) + y1, 0), HH);
            int c0 = min(max(x1, 0), WW);
            sh_r0 = r0;
            sh_c0 = c0;
            sh_nr = min(r1 - r0, WSTRIDE);   // proven <= 22
        }
    }
    __syncthreads();

    int wid  = t >> 5;
    int lane = t & 31;
    float* wbuf = win[wid];

    int r0 = sh_r0, c0 = sh_c0, nr = sh_nr;
    int nc = min(sh_we[PWq - 1] - c0, WSTRIDE);  // window cols, proven <= 22
    const float* fb0 = feats + sh_boff;

    #pragma unroll
    for (int k = 0; k < CPW; ++k) {
        int c = chunk * CPB + wid * CPW + k;
        const float* fc = fb0 + c * (HH * WW);

        // stage window: one coalesced row-load per feature row
        for (int r = 0; r < nr; ++r) {
            const float* row = fc + (r0 + r) * WW + c0;
            for (int j = lane; j < nc; j += 32)
                wbuf[r * WSTRIDE + j] = row[j];
        }
        __syncwarp();

        // 49 bins from smem
        for (int bin = lane; bin < PHq * PWq; bin += 32) {
            int ph = bin / 7;
            int pw = bin - ph * 7;
            int hs = sh_hs[ph] - r0, he = sh_he[ph] - r0;
            int ws = sh_ws[pw] - c0, we = sh_we[pw] - c0;
            float m = -INFINITY;
            for (int h = hs; h < he; ++h) {
                #pragma unroll 4
                for (int w = ws; w < we; ++w)
                    m = fmaxf(m, wbuf[h * WSTRIDE + w]);
            }
            bool nonempty = (he > hs) && (we > ws);
            out[(n * CC + c) * (PHq * PWq) + bin] = nonempty ? m : 0.0f;
        }
        __syncwarp();
    }
}

extern "C" void kernel_launch(void* const* d_in, const int* in_sizes, int n_in,
                              void* d_out, int out_size) {
    // features = large buffer, rois = small buffer (order-robust)
    int fi = 0, ri = 1;
    if (n_in >= 2 && in_sizes[0] < in_sizes[1]) { fi = 1; ri = 0; }
    const float* feats = (const float*)d_in[fi];
    const float* rois  = (const float*)d_in[ri];
    float* out = (float*)d_out;

    int num_rois = out_size / (CC * PHq * PWq);   // 128
    int blocks = num_rois * CHUNKS;               // 1024
    roipool_kernel<<<blocks, 256>>>(feats, rois, out);
}

// round 15
// speedup vs baseline: 1.0182x; 1.0182x over previous
#include <cuda_runtime.h>
#include <math.h>

#define PHq 7
#define PWq 7
#define CC 256
#define HH 50
#define WW 76
#define HW (HH * WW)
#define SCALE 0.0625f
#define CPB 4                   // channels per block
#define CGRP (CC / CPB)         // 64 channel-groups per ROI
#define WROWS 22                // max window rows (proven: ext<=21, +1 ceil spill)
#define WSTRIDE 24              // fixed smem col stride (compile-time div)

__global__ __launch_bounds__(256) void roipool_kernel(const float* __restrict__ feats,
                                                      const float* __restrict__ rois,
                                                      float* __restrict__ out) {
    __shared__ float win[CPB][WROWS * WSTRIDE];   // 4*528*4B = 8448B
    __shared__ int sh_hs[PHq], sh_he[PHq], sh_ws[PWq], sh_we[PWq];
    __shared__ int sh_r0, sh_c0, sh_nr, sh_boff;

    int n  = blockIdx.x >> 6;          // ROI
    int cg = blockIdx.x & 63;          // channel group (4 channels)
    int t  = threadIdx.x;

    if (t <= PHq + PWq) {
        const float* r = rois + n * 5;
        int b  = (int)r[0];
        // round-half-to-even; *2^-4 exact — matches jnp.round(rois*0.0625)
        int x1 = __float2int_rn(r[1] * SCALE);
        int y1 = __float2int_rn(r[2] * SCALE);
        int x2 = __float2int_rn(r[3] * SCALE);
        int y2 = __float2int_rn(r[4] * SCALE);

        // XLA lowers extent/7.0 as extent * fl32(1/7); replicate exactly.
        const float R7 = 1.0f / 7.0f;
        float bin_h = __fmul_rn((float)max(y2 - y1 + 1, 1), R7);
        float bin_w = __fmul_rn((float)max(x2 - x1 + 1, 1), R7);

        if (t < PHq) {
            int hs = (int)floorf(__fmul_rn((float)t, bin_h)) + y1;
            int he = (int)ceilf (__fmul_rn((float)(t + 1), bin_h)) + y1;
            sh_hs[t] = min(max(hs, 0), HH);
            sh_he[t] = min(max(he, 0), HH);
        }
        if (t >= PHq && t < PHq + PWq) {
            int u = t - PHq;
            int ws = (int)floorf(__fmul_rn((float)u, bin_w)) + x1;
            int we = (int)ceilf (__fmul_rn((float)(u + 1), bin_w)) + x1;
            sh_ws[u] = min(max(ws, 0), WW);
            sh_we[u] = min(max(we, 0), WW);
        }
        if (t == PHq + PWq) {
            sh_boff = b * (CC * HW);
            // window bounds: hs[0]==clamp(y1), he[6]==clamp(ceil(7*bin_h)+y1)
            int r0 = min(max(y1, 0), HH);
            int r1 = min(max((int)ceilf(__fmul_rn(7.0f, bin_h)) + y1, 0), HH);
            sh_r0 = r0;
            sh_c0 = min(max(x1, 0), WW);
            sh_nr = r1 - r0;               // proven <= 22
        }
    }
    __syncthreads();

    int r0 = sh_r0, c0 = sh_c0, nr = sh_nr;

    // ---- stage: 64 threads per channel, coalesced gmem -> smem ----
    {
        int ch = t >> 6;                   // 0..3
        int l  = t & 63;
        const float* fc = feats + sh_boff + (cg * CPB + ch) * HW + r0 * WW + c0;
        int total = nr * WSTRIDE;
        for (int i = l; i < total; i += 64) {
            int h = i / WSTRIDE;           // compile-time divisor -> mul/shift
            int w = i - h * WSTRIDE;
            float v = (c0 + w < WW) ? fc[h * WW + w] : 0.0f;  // fault guard
            win[ch][i] = v;
        }
    }
    __syncthreads();

    // ---- reduce: threads 0..195 -> one (channel, bin) each ----
    if (t < CPB * PHq * PWq) {             // 196
        int ch  = t / 49;
        int bin = t - ch * 49;
        int ph  = bin / 7;
        int pw  = bin - ph * 7;

        int hs = sh_hs[ph] - r0, he = sh_he[ph] - r0;
        int ws = sh_ws[pw] - c0, we = sh_we[pw] - c0;
        bool nonempty = (he > hs) && (we > ws);

        const float* wb = win[ch];
        float m = -INFINITY;
        for (int h = hs; h < he; ++h) {
            #pragma unroll 4
            for (int w = ws; w < we; ++w)
                m = fmaxf(m, wb[h * WSTRIDE + w]);
        }
        out[n * (CC * PHq * PWq) + cg * (CPB * PHq * PWq) + t] = nonempty ? m : 0.0f;
    }
}

extern "C" void kernel_launch(void* const* d_in, const int* in_sizes, int n_in,
                              void* d_out, int out_size) {
    // features = large buffer, rois = small buffer (order-robust)
    int fi = 0, ri = 1;
    if (n_in >= 2 && in_sizes[0] < in_sizes[1]) { fi = 1; ri = 0; }
    const float* feats = (const float*)d_in[fi];
    const float* rois  = (const float*)d_in[ri];
    float* out = (float*)d_out;

    int num_rois = out_size / (CC * PHq * PWq);   // 128
    int blocks = num_rois * CGRP;                 // 8192
    roipool_kernel<<<blocks, 256>>>(feats, rois, out);
}